// round 11
// baseline (speedup 1.0000x reference)
#include <cuda_runtime.h>
#include <cstdint>

#define L 320
#define C 128
#define H 4
#define D 32
#define NPOS (L*L)
#define NW2 512   // 384 qkv + 128 gate (pair handled separately)

// ---------------- scratch (device globals; no allocations allowed) ----------------
__device__ float g_zn[NPOS*C];        // layernormed z (tf32-rounded)
__device__ float g_q[H*L*L*D];        // [(r*H+h)*L + i]*D + d   (q pre-scaled by 1/sqrt(D))
__device__ float g_k[H*L*L*D];
__device__ float g_v[H*L*L*D];
__device__ float g_pbI[H*L*L];        // [(h*L + i)*L + j] = pair_bias[i,j,h]
__device__ float g_gate[NPOS*C];      // sigmoid gate
__device__ float g_att[NPOS*C];       // gated attention output (tf32-rounded)
__device__ float g_W[C*NW2];          // packed [c][n] qkv|gate weights (tf32-rounded)
__device__ float g_W2[C*C];           // Wout (tf32-rounded)

// ---------------- tf32 mma.sync helpers ----------------
__device__ __forceinline__ float f2tf32(float x){
    uint32_t r; asm("cvt.rna.tf32.f32 %0, %1;" : "=r"(r) : "f"(x));
    return __uint_as_float(r);
}
__device__ __forceinline__ void mma8(float& d0, float& d1, float& d2, float& d3,
                                     uint32_t a0, uint32_t a1, uint32_t a2, uint32_t a3,
                                     uint32_t b0, uint32_t b1){
    asm("mma.sync.aligned.m16n8k8.row.col.f32.tf32.tf32.f32 "
        "{%0,%1,%2,%3}, {%4,%5,%6,%7}, {%8,%9}, {%0,%1,%2,%3};"
        : "+f"(d0), "+f"(d1), "+f"(d2), "+f"(d3)
        : "r"(a0), "r"(a1), "r"(a2), "r"(a3), "r"(b0), "r"(b1));
}

// ---------------- kernel 1: layernorm (stores tf32-rounded zn) ----------------
__global__ void ln_kernel(const float* __restrict__ z,
                          const float* __restrict__ lng,
                          const float* __restrict__ lnb){
    int p = blockIdx.x;
    int t = threadIdx.x;
    float x = z[p*C + t];
    float s = x, s2 = x*x;
    #pragma unroll
    for (int o = 16; o; o >>= 1){
        s  += __shfl_xor_sync(0xFFFFFFFFu, s,  o);
        s2 += __shfl_xor_sync(0xFFFFFFFFu, s2, o);
    }
    __shared__ float ws[4], ws2[4];
    int w = t >> 5;
    if ((t & 31) == 0){ ws[w] = s; ws2[w] = s2; }
    __syncthreads();
    s  = ws[0] + ws[1] + ws[2] + ws[3];
    s2 = ws2[0] + ws2[1] + ws2[2] + ws2[3];
    float m = s * (1.f/C);
    float v = s2 * (1.f/C) - m*m;
    float r = rsqrtf(v + 1e-5f);
    g_zn[p*C + t] = f2tf32((x - m) * r * lng[t] + lnb[t]);
}

// ---------------- kernel 2: pack weights (qkv|gate -> g_W, Wout -> g_W2), tf32 ----------------
__global__ void pack_kernel(const float* __restrict__ Wqkv,
                            const float* __restrict__ Wgate,
                            const float* __restrict__ Wout){
    int idx = blockIdx.x * blockDim.x + threadIdx.x;
    if (idx < C*NW2){
        int c = idx / NW2, n = idx % NW2;
        float v = (n < 384) ? Wqkv[c*384 + n] : Wgate[c*128 + (n-384)];
        g_W[idx] = f2tf32(v);
    } else if (idx < C*NW2 + C*C){
        int u = idx - C*NW2;
        g_W2[u] = f2tf32(Wout[u]);
    }
}

// ---------------- kernel 3: pair bias (zn @ Wpair), one warp per position ----------------
__global__ void pair_kernel(const float* __restrict__ Wpair){
    int wid = threadIdx.x >> 5;
    int lane = threadIdx.x & 31;
    int p = blockIdx.x * 8 + wid;
    float4 zz = *(const float4*)&g_zn[(size_t)p*C + lane*4];
    float s0 = 0.f, s1 = 0.f, s2 = 0.f, s3 = 0.f;
    #pragma unroll
    for (int k = 0; k < 4; k++){
        float zc = (&zz.x)[k];
        const float* wp = &Wpair[(lane*4 + k)*4];
        s0 += zc * wp[0]; s1 += zc * wp[1];
        s2 += zc * wp[2]; s3 += zc * wp[3];
    }
    #pragma unroll
    for (int o = 16; o; o >>= 1){
        s0 += __shfl_xor_sync(0xFFFFFFFFu, s0, o);
        s1 += __shfl_xor_sync(0xFFFFFFFFu, s1, o);
        s2 += __shfl_xor_sync(0xFFFFFFFFu, s2, o);
        s3 += __shfl_xor_sync(0xFFFFFFFFu, s3, o);
    }
    if (lane < 4){
        float sv = (lane == 0) ? s0 : (lane == 1) ? s1 : (lane == 2) ? s2 : s3;
        int i = p / L, j = p - i*L;
        g_pbI[((size_t)(lane*L + i))*L + j] = sv;
    }
}

// ---------------- fragment-major tf32 GEMM (gemm0: proj, gemm1: output) ----------------
// BM=128, BN=64, K=128 resident. Fragment-major smem:
//   As[mt8][kt16][lane32][slot4]  (A 16x8 tile -> one LDS.128 per thread)
//   Ws[kt16][nt8][lane32][slot2]  (B 8x8 tile  -> one LDS.64  per thread)
#define GEMM_SMEM ((8*16*32*4 + 16*8*32*2)*4)

__device__ __forceinline__ void epi2(int p, int n, float v0, float v1,
                                     const float* __restrict__ bgate){
    int r = p / L, i = p - r*L;
    if (n < 384){
        int part = n >> 7, rem = n & 127;
        int h = rem >> 5, d = rem & 31;
        size_t idx = ((size_t)(r*H + h)*L + i)*D + d;
        if (part == 0){
            g_q[idx]   = v0 * 0.17677669529663687f;
            g_q[idx+1] = v1 * 0.17677669529663687f;
        } else if (part == 1){
            g_k[idx] = v0; g_k[idx+1] = v1;
        } else {
            g_v[idx] = v0; g_v[idx+1] = v1;
        }
    } else {
        int c = n - 384;
        g_gate[(size_t)p*C + c    ] = 1.f / (1.f + __expf(-(v0 + bgate[c])));
        g_gate[(size_t)p*C + c + 1] = 1.f / (1.f + __expf(-(v1 + bgate[c+1])));
    }
}

template<int MODE>
__global__ void __launch_bounds__(256)
gemm_mma(const float* __restrict__ bias, float* __restrict__ out){
    constexpr int NW = (MODE == 0) ? NW2 : C;
    const float* __restrict__ A = (MODE == 0) ? g_zn : g_att;
    const float* __restrict__ W = (MODE == 0) ? g_W  : g_W2;

    extern __shared__ float smf[];
    float* As = smf;                    // 8*16*32*4 = 16384 floats
    float* Ws = smf + 8*16*32*4;        // 16*8*32*2 = 8192 floats

    const int tid = threadIdx.x;
    const int n0 = blockIdx.x * 64;
    const int m0 = blockIdx.y * 128;
    const int lane = tid & 31, wid = tid >> 5;
    const int g = lane >> 2, qr = lane & 3;
    const int wm_t = (wid & 3) * 2;     // m-tile base (2 tiles of 16 rows)
    const int wn_t = (wid >> 2) * 4;    // n-tile base (4 tiles of 8 cols)

    // ---- fill A (128x128) fragment-major ----
    {
        const float4* ag = (const float4*)&A[(size_t)m0*C];
        #pragma unroll
        for (int u = tid; u < 4096; u += 256){
            int row = u >> 5, c4 = (u & 31) << 2;
            float4 a = ag[u];
            int mt = row >> 4, ip = row & 15;
            int kt = c4 >> 3;
            int slot = (ip >> 3) + ((c4 & 4) ? 2 : 0);
            float* dst = &As[(((mt*16 + kt)*32) + ((ip & 7) << 2))*4 + slot];
            dst[0]  = a.x; dst[4]  = a.y; dst[8]  = a.z; dst[12] = a.w;
        }
        #pragma unroll
        for (int u = tid; u < 2048; u += 256){
            int row = u >> 4, n4 = (u & 15) << 2;
            float4 w = *(const float4*)&W[row*NW + n0 + n4];
            int kt = row >> 3, kk = row & 7;
            int slot = kk >> 2;
            int nt = n4 >> 3;
            int lane0 = ((n4 & 7) << 2) | (kk & 3);
            float* dst = &Ws[((kt*8 + nt)*32 + lane0)*2 + slot];
            dst[0] = w.x; dst[8] = w.y; dst[16] = w.z; dst[24] = w.w;
        }
    }
    __syncthreads();

    float o[2][4][4];
    #pragma unroll
    for (int mt = 0; mt < 2; mt++)
        #pragma unroll
        for (int nt = 0; nt < 4; nt++)
            #pragma unroll
            for (int q = 0; q < 4; q++) o[mt][nt][q] = 0.f;

    #pragma unroll
    for (int kt = 0; kt < 16; kt++){
        float4 af[2];
        float2 bf[4];
        #pragma unroll
        for (int mt = 0; mt < 2; mt++)
            af[mt] = *(const float4*)&As[(((wm_t + mt)*16 + kt)*32 + lane)*4];
        #pragma unroll
        for (int nt = 0; nt < 4; nt++)
            bf[nt] = *(const float2*)&Ws[((kt*8) + wn_t + nt)*64 + lane*2];
        #pragma unroll
        for (int mt = 0; mt < 2; mt++){
            uint32_t a0 = __float_as_uint(af[mt].x), a1 = __float_as_uint(af[mt].y);
            uint32_t a2 = __float_as_uint(af[mt].z), a3 = __float_as_uint(af[mt].w);
            #pragma unroll
            for (int nt = 0; nt < 4; nt++)
                mma8(o[mt][nt][0], o[mt][nt][1], o[mt][nt][2], o[mt][nt][3],
                     a0, a1, a2, a3,
                     __float_as_uint(bf[nt].x), __float_as_uint(bf[nt].y));
        }
    }

    #pragma unroll
    for (int mt = 0; mt < 2; mt++){
        #pragma unroll
        for (int nt = 0; nt < 4; nt++){
            int n = n0 + (wn_t + nt)*8 + qr*2;
            int ma = m0 + (wm_t + mt)*16 + g;
            if (MODE == 0){
                epi2(ma,     n, o[mt][nt][0], o[mt][nt][1], bias);
                epi2(ma + 8, n, o[mt][nt][2], o[mt][nt][3], bias);
            } else {
                float b0 = bias[n], b1 = bias[n+1];
                out[(size_t)(ma  )*C + n  ] = o[mt][nt][0] + b0;
                out[(size_t)(ma  )*C + n+1] = o[mt][nt][1] + b1;
                out[(size_t)(ma+8)*C + n  ] = o[mt][nt][2] + b0;
                out[(size_t)(ma+8)*C + n+1] = o[mt][nt][3] + b1;
            }
        }
    }
}

// ---------------- attention: tf32 mma.sync flash, fragment-major K/V ----------------
// Kf[jt40][kt4][lane32][slot2]  (S-phase B tiles: n=j, k=d)
// Vf[jt40][dt4][lane32][slot2]  (PV-phase B tiles: k=j, n=d)
#define KF_FLOATS (40*4*32*2)
#define SMEM_ATTN (2*KF_FLOATS*4)

__global__ void __launch_bounds__(640, 1)
attn_kernel(){
    extern __shared__ float sm[];
    float* Kf = sm;
    float* Vf = sm + KF_FLOATS;

    const int tid = threadIdx.x;
    const int lane = tid & 31;
    const int g = lane >> 2;
    const int qr = lane & 3;
    const int i0 = (tid >> 5) * 16;
    const int r = blockIdx.x, h = blockIdx.y;
    const int rh = r*H + h;

    // ---- fill K/V fragment-major (tf32-converted) ----
    {
        const float4* kg = (const float4*)&g_k[(size_t)rh*L*D];
        const float4* vg = (const float4*)&g_v[(size_t)rh*L*D];
        for (int u = tid; u < L*D/4; u += 640){
            int j = u >> 3, d4 = (u & 7) << 2;
            float4 kv = kg[u];
            float4 vv = vg[u];
            int jt = j >> 3;
            // K: element (j,d): lane=((j&7)<<2)|(d&3), slot=(d&7)>>2, kt=d>>3
            {
                int slot = (d4 & 4) >> 2;
                float* kd = &Kf[((jt*4 + (d4 >> 3))*32 + ((j & 7) << 2))*2 + slot];
                kd[0] = f2tf32(kv.x); kd[2] = f2tf32(kv.y);
                kd[4] = f2tf32(kv.z); kd[6] = f2tf32(kv.w);
            }
            // V: element (j,d): lane=((d&7)<<2)|(j&3), slot=(j&7)>>2, dt=d>>3
            {
                int slot = (j & 7) >> 2;
                int lane0 = ((d4 & 7) << 2) | (j & 3);
                float* vd = &Vf[((jt*4 + (d4 >> 3))*32 + lane0)*2 + slot];
                vd[0] = f2tf32(vv.x); vd[8]  = f2tf32(vv.y);
                vd[16] = f2tf32(vv.z); vd[24] = f2tf32(vv.w);
            }
        }
    }

    // ---- Q fragments (register-resident, tf32) ----
    uint32_t qa[4][4];
    {
        const float* qbase = g_q + ((size_t)rh*L + i0)*D;
        #pragma unroll
        for (int t = 0; t < 4; t++){
            qa[t][0] = __float_as_uint(f2tf32(__ldg(&qbase[(g   )*D + 8*t + qr    ])));
            qa[t][1] = __float_as_uint(f2tf32(__ldg(&qbase[(g+8 )*D + 8*t + qr    ])));
            qa[t][2] = __float_as_uint(f2tf32(__ldg(&qbase[(g   )*D + 8*t + qr + 4])));
            qa[t][3] = __float_as_uint(f2tf32(__ldg(&qbase[(g+8 )*D + 8*t + qr + 4])));
        }
    }
    __syncthreads();

    const float* bp0 = g_pbI + ((size_t)(h*L + i0 + g    ))*L;
    const float* bp1 = g_pbI + ((size_t)(h*L + i0 + g + 8))*L;

    float o[4][4];
    #pragma unroll
    for (int n = 0; n < 4; n++)
        #pragma unroll
        for (int q = 0; q < 4; q++) o[n][q] = 0.f;
    float lsum0 = 0.f, lsum1 = 0.f;

    const int srcA = (lane & ~3) | (qr >> 1);
    const int srcB = srcA + 2;
    const bool oddl = lane & 1;

    for (int c = 0; c < 5; c++){
        float pr0[8], pr1[8], pr2[8], pr3[8];
        #pragma unroll
        for (int n = 0; n < 8; n++){
            float s0 = 0.f, s1 = 0.f, s2 = 0.f, s3 = 0.f;
            const float* kb = &Kf[((8*c + n)*4)*64 + lane*2];
            #pragma unroll
            for (int t = 0; t < 4; t++){
                float2 bb2 = *(const float2*)&kb[t*64];
                mma8(s0, s1, s2, s3, qa[t][0], qa[t][1], qa[t][2], qa[t][3],
                     __float_as_uint(bb2.x), __float_as_uint(bb2.y));
            }
            int j0 = 64*c + 8*n + qr*2;
            float2 ba = *(const float2*)&bp0[j0];
            float2 bb = *(const float2*)&bp1[j0];
            float p0 = f2tf32(__expf(fminf(s0 + ba.x, 60.f)));
            float p1 = f2tf32(__expf(fminf(s1 + ba.y, 60.f)));
            float p2 = f2tf32(__expf(fminf(s2 + bb.x, 60.f)));
            float p3 = f2tf32(__expf(fminf(s3 + bb.y, 60.f)));
            lsum0 += p0 + p1;
            lsum1 += p2 + p3;
            pr0[n] = p0; pr1[n] = p1; pr2[n] = p2; pr3[n] = p3;
        }
        #pragma unroll
        for (int t = 0; t < 8; t++){
            float v0a = __shfl_sync(0xFFFFFFFFu, pr0[t], srcA);
            float v1a = __shfl_sync(0xFFFFFFFFu, pr1[t], srcA);
            float v2a = __shfl_sync(0xFFFFFFFFu, pr2[t], srcA);
            float v3a = __shfl_sync(0xFFFFFFFFu, pr3[t], srcA);
            float v0b = __shfl_sync(0xFFFFFFFFu, pr0[t], srcB);
            float v1b = __shfl_sync(0xFFFFFFFFu, pr1[t], srcB);
            float v2b = __shfl_sync(0xFFFFFFFFu, pr2[t], srcB);
            float v3b = __shfl_sync(0xFFFFFFFFu, pr3[t], srcB);
            uint32_t A0 = __float_as_uint(oddl ? v1a : v0a);
            uint32_t A1 = __float_as_uint(oddl ? v3a : v2a);
            uint32_t A2 = __float_as_uint(oddl ? v1b : v0b);
            uint32_t A3 = __float_as_uint(oddl ? v3b : v2b);
            const float* vb = &Vf[((8*c + t)*4)*64 + lane*2];
            #pragma unroll
            for (int n = 0; n < 4; n++){
                float2 bb2 = *(const float2*)&vb[n*64];
                mma8(o[n][0], o[n][1], o[n][2], o[n][3], A0, A1, A2, A3,
                     __float_as_uint(bb2.x), __float_as_uint(bb2.y));
            }
        }
    }

    lsum0 += __shfl_xor_sync(0xFFFFFFFFu, lsum0, 1);
    lsum0 += __shfl_xor_sync(0xFFFFFFFFu, lsum0, 2);
    lsum1 += __shfl_xor_sync(0xFFFFFFFFu, lsum1, 1);
    lsum1 += __shfl_xor_sync(0xFFFFFFFFu, lsum1, 2);
    float inv0 = 1.f / lsum0;
    float inv1 = 1.f / lsum1;

    int ig0 = i0 + g, ig1 = i0 + g + 8;
    size_t ob0 = (size_t)(r*L + ig0)*C + h*D;
    size_t ob1 = (size_t)(r*L + ig1)*C + h*D;
    #pragma unroll
    for (int n = 0; n < 4; n++){
        int d0 = 8*n + qr*2;
        float2 g0 = *(const float2*)&g_gate[ob0 + d0];
        float2 g1 = *(const float2*)&g_gate[ob1 + d0];
        float2 w0, w1;
        w0.x = f2tf32(o[n][0] * inv0 * g0.x);
        w0.y = f2tf32(o[n][1] * inv0 * g0.y);
        w1.x = f2tf32(o[n][2] * inv1 * g1.x);
        w1.y = f2tf32(o[n][3] * inv1 * g1.y);
        *(float2*)&g_att[ob0 + d0] = w0;
        *(float2*)&g_att[ob1 + d0] = w1;
    }
}

// ---------------- launch ----------------
extern "C" void kernel_launch(void* const* d_in, const int* in_sizes, int n_in,
                              void* d_out, int out_size){
    const float* z     = (const float*)d_in[0];
    const float* ln_g  = (const float*)d_in[1];
    const float* ln_b  = (const float*)d_in[2];
    const float* Wqkv  = (const float*)d_in[3];
    const float* Wpair = (const float*)d_in[4];
    const float* Wgate = (const float*)d_in[5];
    const float* bgate = (const float*)d_in[6];
    const float* Wout  = (const float*)d_in[7];
    const float* bout  = (const float*)d_in[8];
    float* out = (float*)d_out;

    static bool attr_set = false;
    if (!attr_set){
        cudaFuncSetAttribute(attn_kernel, cudaFuncAttributeMaxDynamicSharedMemorySize,
                             SMEM_ATTN);
        cudaFuncSetAttribute(gemm_mma<0>, cudaFuncAttributeMaxDynamicSharedMemorySize,
                             GEMM_SMEM);
        cudaFuncSetAttribute(gemm_mma<1>, cudaFuncAttributeMaxDynamicSharedMemorySize,
                             GEMM_SMEM);
        attr_set = true;
    }

    ln_kernel<<<NPOS, 128>>>(z, ln_g, ln_b);
    pack_kernel<<<(C*(NW2 + C) + 255)/256, 256>>>(Wqkv, Wgate, Wout);
    pair_kernel<<<NPOS/8, 256>>>(Wpair);
    gemm_mma<0><<<dim3(NW2/64, NPOS/128), 256, GEMM_SMEM>>>(bgate, nullptr);
    attn_kernel<<<dim3(L, H), 640, SMEM_ATTN>>>();
    gemm_mma<1><<<dim3(C/64, NPOS/128), 256, GEMM_SMEM>>>(bout, out);
}

// round 16
// speedup vs baseline: 1.1520x; 1.1520x over previous
#include <cuda_runtime.h>
#include <cstdint>

#define L 320
#define C 128
#define H 4
#define D 32
#define NPOS (L*L)
#define NW2 512   // 384 qkv + 128 gate (pair handled separately)

// ---------------- scratch (device globals; no allocations allowed) ----------------
__device__ float g_zn[NPOS*C];        // layernormed z (tf32-rounded)
__device__ float g_q[H*L*L*D];        // [(r*H+h)*L + i]*D + d   (q pre-scaled by 1/sqrt(D))
__device__ float g_k[H*L*L*D];
__device__ float g_v[H*L*L*D];
__device__ float g_pbI[H*L*L];        // [(h*L + i)*L + j] = pair_bias[i,j,h]
__device__ float g_gate[NPOS*C];      // sigmoid gate
__device__ float g_att[NPOS*C];       // gated attention output (fp32; rounded in gemm1 fill)
__device__ float g_W[C*NW2];          // packed [c][n] qkv|gate weights (tf32-rounded)
__device__ float g_W2[C*C];           // Wout (tf32-rounded)

// ---------------- tf32 mma.sync helpers ----------------
__device__ __forceinline__ float f2tf32(float x){
    uint32_t r; asm("cvt.rna.tf32.f32 %0, %1;" : "=r"(r) : "f"(x));
    return __uint_as_float(r);
}
__device__ __forceinline__ void mma8(float& d0, float& d1, float& d2, float& d3,
                                     uint32_t a0, uint32_t a1, uint32_t a2, uint32_t a3,
                                     uint32_t b0, uint32_t b1){
    asm("mma.sync.aligned.m16n8k8.row.col.f32.tf32.tf32.f32 "
        "{%0,%1,%2,%3}, {%4,%5,%6,%7}, {%8,%9}, {%0,%1,%2,%3};"
        : "+f"(d0), "+f"(d1), "+f"(d2), "+f"(d3)
        : "r"(a0), "r"(a1), "r"(a2), "r"(a3), "r"(b0), "r"(b1));
}
__device__ __forceinline__ void ldsm4(uint32_t& r0, uint32_t& r1,
                                      uint32_t& r2, uint32_t& r3, uint32_t addr){
    asm volatile("ldmatrix.sync.aligned.m8n8.x4.shared.b16 {%0,%1,%2,%3}, [%4];"
        : "=r"(r0), "=r"(r1), "=r"(r2), "=r"(r3) : "r"(addr));
}
__device__ __forceinline__ uint32_t smem_u32(const void* p){
    uint32_t a;
    asm("{ .reg .u64 t; cvta.to.shared.u64 t, %1; cvt.u32.u64 %0, t; }" : "=r"(a) : "l"(p));
    return a;
}

// ---------------- kernel 1: layernorm (stores tf32-rounded zn) ----------------
__global__ void ln_kernel(const float* __restrict__ z,
                          const float* __restrict__ lng,
                          const float* __restrict__ lnb){
    int p = blockIdx.x;
    int t = threadIdx.x;
    float x = z[p*C + t];
    float s = x, s2 = x*x;
    #pragma unroll
    for (int o = 16; o; o >>= 1){
        s  += __shfl_xor_sync(0xFFFFFFFFu, s,  o);
        s2 += __shfl_xor_sync(0xFFFFFFFFu, s2, o);
    }
    __shared__ float ws[4], ws2[4];
    int w = t >> 5;
    if ((t & 31) == 0){ ws[w] = s; ws2[w] = s2; }
    __syncthreads();
    s  = ws[0] + ws[1] + ws[2] + ws[3];
    s2 = ws2[0] + ws2[1] + ws2[2] + ws2[3];
    float m = s * (1.f/C);
    float v = s2 * (1.f/C) - m*m;
    float r = rsqrtf(v + 1e-5f);
    g_zn[p*C + t] = f2tf32((x - m) * r * lng[t] + lnb[t]);
}

// ---------------- kernel 2: pack weights (qkv|gate -> g_W, Wout -> g_W2), tf32 ----------------
__global__ void pack_kernel(const float* __restrict__ Wqkv,
                            const float* __restrict__ Wgate,
                            const float* __restrict__ Wout){
    int idx = blockIdx.x * blockDim.x + threadIdx.x;
    if (idx < C*NW2){
        int c = idx / NW2, n = idx % NW2;
        float v = (n < 384) ? Wqkv[c*384 + n] : Wgate[c*128 + (n-384)];
        g_W[idx] = f2tf32(v);
    } else if (idx < C*NW2 + C*C){
        int u = idx - C*NW2;
        g_W2[u] = f2tf32(Wout[u]);
    }
}

// ---------------- kernel 3: pair bias (zn @ Wpair), one warp per position ----------------
__global__ void pair_kernel(const float* __restrict__ Wpair){
    int wid = threadIdx.x >> 5;
    int lane = threadIdx.x & 31;
    int p = blockIdx.x * 8 + wid;
    float4 zz = *(const float4*)&g_zn[(size_t)p*C + lane*4];
    float s0 = 0.f, s1 = 0.f, s2 = 0.f, s3 = 0.f;
    #pragma unroll
    for (int k = 0; k < 4; k++){
        float zc = (&zz.x)[k];
        const float* wp = &Wpair[(lane*4 + k)*4];
        s0 += zc * wp[0]; s1 += zc * wp[1];
        s2 += zc * wp[2]; s3 += zc * wp[3];
    }
    #pragma unroll
    for (int o = 16; o; o >>= 1){
        s0 += __shfl_xor_sync(0xFFFFFFFFu, s0, o);
        s1 += __shfl_xor_sync(0xFFFFFFFFu, s1, o);
        s2 += __shfl_xor_sync(0xFFFFFFFFu, s2, o);
        s3 += __shfl_xor_sync(0xFFFFFFFFu, s3, o);
    }
    if (lane < 4){
        float sv = (lane == 0) ? s0 : (lane == 1) ? s1 : (lane == 2) ? s2 : s3;
        int i = p / L, j = p - i*L;
        g_pbI[((size_t)(lane*L + i))*L + j] = sv;
    }
}

// ---------------- tf32 mma GEMM: BM=128, BN=64, K=128 resident ----------------
// 4 warps (128 thr), warp tile 32m x 64n, 2 CTAs/SM.
// A smem [m][k] stride 132 (ldmatrix-aligned, conflict-free fills & LDSM).
// W smem [k][n] stride 72 (8qr+g distinct mod 32 -> conflict-free scalar B loads).
#define AS_STRIDE 132
#define WS_STRIDE 72
#define GEMM_SMEM ((128*AS_STRIDE + 128*WS_STRIDE)*4)

__device__ __forceinline__ void epi2(int p, int n, float v0, float v1,
                                     const float* __restrict__ bgate){
    int r = p / L, i = p - r*L;
    if (n < 384){
        int part = n >> 7, rem = n & 127;
        int h = rem >> 5, d = rem & 31;
        size_t idx = ((size_t)(r*H + h)*L + i)*D + d;
        if (part == 0){
            g_q[idx]   = v0 * 0.17677669529663687f;
            g_q[idx+1] = v1 * 0.17677669529663687f;
        } else if (part == 1){
            g_k[idx] = v0; g_k[idx+1] = v1;
        } else {
            g_v[idx] = v0; g_v[idx+1] = v1;
        }
    } else {
        int c = n - 384;
        g_gate[(size_t)p*C + c    ] = 1.f / (1.f + __expf(-(v0 + bgate[c])));
        g_gate[(size_t)p*C + c + 1] = 1.f / (1.f + __expf(-(v1 + bgate[c+1])));
    }
}

template<int MODE>
__global__ void __launch_bounds__(128, 2)
gemm_mma(const float* __restrict__ bias, float* __restrict__ out){
    constexpr int NW = (MODE == 0) ? NW2 : C;
    const float* __restrict__ A = (MODE == 0) ? g_zn : g_att;
    const float* __restrict__ W = (MODE == 0) ? g_W  : g_W2;

    extern __shared__ float smf[];
    float* As = smf;                     // [128][132]
    float* Ws = smf + 128*AS_STRIDE;     // [128][72]

    const int tid = threadIdx.x;
    const int n0 = blockIdx.x * 64;
    const int m0 = blockIdx.y * 128;
    const int lane = tid & 31, wid = tid >> 5;
    const int g = lane >> 2, qr = lane & 3;
    const int wm = wid * 32;

    // ---- fill A (128x128) ----
    {
        const float4* ag = (const float4*)&A[(size_t)m0*C];
        #pragma unroll
        for (int u = tid; u < 4096; u += 128){
            int row = u >> 5, c4 = (u & 31) << 2;
            float4 a = ag[u];
            if (MODE == 1){
                a.x = f2tf32(a.x); a.y = f2tf32(a.y);
                a.z = f2tf32(a.z); a.w = f2tf32(a.w);
            }
            *(float4*)&As[row*AS_STRIDE + c4] = a;
        }
        // ---- fill W (128k x 64n) ----
        #pragma unroll
        for (int u = tid; u < 2048; u += 128){
            int row = u >> 4, n4 = (u & 15) << 2;
            *(float4*)&Ws[row*WS_STRIDE + n4] =
                *(const float4*)&W[row*NW + n0 + n4];
        }
    }
    __syncthreads();

    float o[2][8][4];
    #pragma unroll
    for (int mt = 0; mt < 2; mt++)
        #pragma unroll
        for (int nt = 0; nt < 8; nt++)
            #pragma unroll
            for (int q = 0; q < 4; q++) o[mt][nt][q] = 0.f;

    // ldmatrix base addresses (lane-dependent), advance 32B per kt
    uint32_t abase0 = smem_u32(As) +
        (uint32_t)(((wm + (lane & 15))*AS_STRIDE + ((lane >> 4) << 2)) * 4);
    uint32_t abase1 = abase0 + 16*AS_STRIDE*4;

    #pragma unroll
    for (int kt = 0; kt < 16; kt++){
        uint32_t a0[4], a1[4];
        ldsm4(a0[0], a0[1], a0[2], a0[3], abase0 + kt*32);
        ldsm4(a1[0], a1[1], a1[2], a1[3], abase1 + kt*32);

        const float* w0 = &Ws[(kt*8 + qr)*WS_STRIDE + g];
        #pragma unroll
        for (int nt = 0; nt < 8; nt++){
            uint32_t b0 = __float_as_uint(w0[nt*8]);
            uint32_t b1 = __float_as_uint(w0[4*WS_STRIDE + nt*8]);
            mma8(o[0][nt][0], o[0][nt][1], o[0][nt][2], o[0][nt][3],
                 a0[0], a0[1], a0[2], a0[3], b0, b1);
            mma8(o[1][nt][0], o[1][nt][1], o[1][nt][2], o[1][nt][3],
                 a1[0], a1[1], a1[2], a1[3], b0, b1);
        }
    }

    #pragma unroll
    for (int mt = 0; mt < 2; mt++){
        #pragma unroll
        for (int nt = 0; nt < 8; nt++){
            int n = n0 + nt*8 + qr*2;
            int ma = m0 + wm + mt*16 + g;
            if (MODE == 0){
                epi2(ma,     n, o[mt][nt][0], o[mt][nt][1], bias);
                epi2(ma + 8, n, o[mt][nt][2], o[mt][nt][3], bias);
            } else {
                float b0 = bias[n], b1 = bias[n+1];
                out[(size_t)(ma  )*C + n  ] = o[mt][nt][0] + b0;
                out[(size_t)(ma  )*C + n+1] = o[mt][nt][1] + b1;
                out[(size_t)(ma+8)*C + n  ] = o[mt][nt][2] + b0;
                out[(size_t)(ma+8)*C + n+1] = o[mt][nt][3] + b1;
            }
        }
    }
}

// ---------------- attention: tf32 mma.sync flash (round-10 version) ----------------
#define KV_STRIDE 36
#define SMEM_ATTN (2*L*KV_STRIDE*4)

__global__ void __launch_bounds__(640, 1)
attn_kernel(){
    extern __shared__ float sm[];
    float* Ks = sm;
    float* Vs = sm + L*KV_STRIDE;

    const int tid = threadIdx.x;
    const int lane = tid & 31;
    const int g = lane >> 2;
    const int qr = lane & 3;
    const int i0 = (tid >> 5) * 16;
    const int r = blockIdx.x, h = blockIdx.y;
    const int rh = r*H + h;

    {
        const float4* kg = (const float4*)&g_k[(size_t)rh*L*D];
        const float4* vg = (const float4*)&g_v[(size_t)rh*L*D];
        for (int u = tid; u < L*D/4; u += 640){
            int j = u >> 3, d4 = (u & 7) << 2;
            float4 kv = kg[u];
            float4 vv = vg[u];
            float* kd = &Ks[j*KV_STRIDE + d4];
            float* vd = &Vs[j*KV_STRIDE + d4];
            kd[0] = f2tf32(kv.x); kd[1] = f2tf32(kv.y);
            kd[2] = f2tf32(kv.z); kd[3] = f2tf32(kv.w);
            vd[0] = f2tf32(vv.x); vd[1] = f2tf32(vv.y);
            vd[2] = f2tf32(vv.z); vd[3] = f2tf32(vv.w);
        }
    }

    uint32_t qa[4][4];
    {
        const float* qbase = g_q + ((size_t)rh*L + i0)*D;
        #pragma unroll
        for (int t = 0; t < 4; t++){
            qa[t][0] = __float_as_uint(f2tf32(__ldg(&qbase[(g   )*D + 8*t + qr    ])));
            qa[t][1] = __float_as_uint(f2tf32(__ldg(&qbase[(g+8 )*D + 8*t + qr    ])));
            qa[t][2] = __float_as_uint(f2tf32(__ldg(&qbase[(g   )*D + 8*t + qr + 4])));
            qa[t][3] = __float_as_uint(f2tf32(__ldg(&qbase[(g+8 )*D + 8*t + qr + 4])));
        }
    }
    __syncthreads();

    const float* bp0 = g_pbI + ((size_t)(h*L + i0 + g    ))*L;
    const float* bp1 = g_pbI + ((size_t)(h*L + i0 + g + 8))*L;

    float o[4][4];
    #pragma unroll
    for (int n = 0; n < 4; n++)
        #pragma unroll
        for (int q = 0; q < 4; q++) o[n][q] = 0.f;
    float lsum0 = 0.f, lsum1 = 0.f;

    const int srcA = (lane & ~3) | (qr >> 1);
    const int srcB = srcA + 2;
    const bool oddl = lane & 1;

    for (int c = 0; c < 5; c++){
        const int jc = 64*c;
        float pr0[8], pr1[8], pr2[8], pr3[8];
        #pragma unroll
        for (int n = 0; n < 8; n++){
            float s0 = 0.f, s1 = 0.f, s2 = 0.f, s3 = 0.f;
            const float* kb = &Ks[(jc + 8*n + g)*KV_STRIDE + qr];
            #pragma unroll
            for (int t = 0; t < 4; t++){
                uint32_t b0 = __float_as_uint(kb[8*t]);
                uint32_t b1 = __float_as_uint(kb[8*t + 4]);
                mma8(s0, s1, s2, s3, qa[t][0], qa[t][1], qa[t][2], qa[t][3], b0, b1);
            }
            int j0 = jc + 8*n + qr*2;
            float2 ba = *(const float2*)&bp0[j0];
            float2 bb = *(const float2*)&bp1[j0];
            float p0 = f2tf32(__expf(fminf(s0 + ba.x, 60.f)));
            float p1 = f2tf32(__expf(fminf(s1 + ba.y, 60.f)));
            float p2 = f2tf32(__expf(fminf(s2 + bb.x, 60.f)));
            float p3 = f2tf32(__expf(fminf(s3 + bb.y, 60.f)));
            lsum0 += p0 + p1;
            lsum1 += p2 + p3;
            pr0[n] = p0; pr1[n] = p1; pr2[n] = p2; pr3[n] = p3;
        }
        #pragma unroll
        for (int t = 0; t < 8; t++){
            float v0a = __shfl_sync(0xFFFFFFFFu, pr0[t], srcA);
            float v1a = __shfl_sync(0xFFFFFFFFu, pr1[t], srcA);
            float v2a = __shfl_sync(0xFFFFFFFFu, pr2[t], srcA);
            float v3a = __shfl_sync(0xFFFFFFFFu, pr3[t], srcA);
            float v0b = __shfl_sync(0xFFFFFFFFu, pr0[t], srcB);
            float v1b = __shfl_sync(0xFFFFFFFFu, pr1[t], srcB);
            float v2b = __shfl_sync(0xFFFFFFFFu, pr2[t], srcB);
            float v3b = __shfl_sync(0xFFFFFFFFu, pr3[t], srcB);
            uint32_t A0 = __float_as_uint(oddl ? v1a : v0a);
            uint32_t A1 = __float_as_uint(oddl ? v3a : v2a);
            uint32_t A2 = __float_as_uint(oddl ? v1b : v0b);
            uint32_t A3 = __float_as_uint(oddl ? v3b : v2b);
            const float* vb0 = &Vs[(jc + 8*t + qr    )*KV_STRIDE + g];
            const float* vb1 = &Vs[(jc + 8*t + qr + 4)*KV_STRIDE + g];
            #pragma unroll
            for (int n = 0; n < 4; n++){
                uint32_t b0 = __float_as_uint(vb0[8*n]);
                uint32_t b1 = __float_as_uint(vb1[8*n]);
                mma8(o[n][0], o[n][1], o[n][2], o[n][3], A0, A1, A2, A3, b0, b1);
            }
        }
    }

    lsum0 += __shfl_xor_sync(0xFFFFFFFFu, lsum0, 1);
    lsum0 += __shfl_xor_sync(0xFFFFFFFFu, lsum0, 2);
    lsum1 += __shfl_xor_sync(0xFFFFFFFFu, lsum1, 1);
    lsum1 += __shfl_xor_sync(0xFFFFFFFFu, lsum1, 2);
    float inv0 = 1.f / lsum0;
    float inv1 = 1.f / lsum1;

    int ig0 = i0 + g, ig1 = i0 + g + 8;
    size_t ob0 = (size_t)(r*L + ig0)*C + h*D;
    size_t ob1 = (size_t)(r*L + ig1)*C + h*D;
    #pragma unroll
    for (int n = 0; n < 4; n++){
        int d0 = 8*n + qr*2;
        float2 g0 = *(const float2*)&g_gate[ob0 + d0];
        float2 g1 = *(const float2*)&g_gate[ob1 + d0];
        float2 w0, w1;
        w0.x = o[n][0] * inv0 * g0.x;
        w0.y = o[n][1] * inv0 * g0.y;
        w1.x = o[n][2] * inv1 * g1.x;
        w1.y = o[n][3] * inv1 * g1.y;
        *(float2*)&g_att[ob0 + d0] = w0;
        *(float2*)&g_att[ob1 + d0] = w1;
    }
}

// ---------------- launch ----------------
extern "C" void kernel_launch(void* const* d_in, const int* in_sizes, int n_in,
                              void* d_out, int out_size){
    const float* z     = (const float*)d_in[0];
    const float* ln_g  = (const float*)d_in[1];
    const float* ln_b  = (const float*)d_in[2];
    const float* Wqkv  = (const float*)d_in[3];
    const float* Wpair = (const float*)d_in[4];
    const float* Wgate = (const float*)d_in[5];
    const float* bgate = (const float*)d_in[6];
    const float* Wout  = (const float*)d_in[7];
    const float* bout  = (const float*)d_in[8];
    float* out = (float*)d_out;

    static bool attr_set = false;
    if (!attr_set){
        cudaFuncSetAttribute(attn_kernel, cudaFuncAttributeMaxDynamicSharedMemorySize,
                             SMEM_ATTN);
        cudaFuncSetAttribute(gemm_mma<0>, cudaFuncAttributeMaxDynamicSharedMemorySize,
                             GEMM_SMEM);
        cudaFuncSetAttribute(gemm_mma<1>, cudaFuncAttributeMaxDynamicSharedMemorySize,
                             GEMM_SMEM);
        attr_set = true;
    }

    ln_kernel<<<NPOS, 128>>>(z, ln_g, ln_b);
    pack_kernel<<<(C*(NW2 + C) + 255)/256, 256>>>(Wqkv, Wgate, Wout);
    pair_kernel<<<NPOS/8, 256>>>(Wpair);
    gemm_mma<0><<<dim3(NW2/64, NPOS/128), 128, GEMM_SMEM>>>(bgate, nullptr);
    attn_kernel<<<dim3(L, H), 640, SMEM_ATTN>>>();
    gemm_mma<1><<<dim3(C/64, NPOS/128), 128, GEMM_SMEM>>>(bout, out);
}